// round 16
// baseline (speedup 1.0000x reference)
#include <cuda_runtime.h>
#include <cuda_fp16.h>
#include <cstdint>

// Problem constants
#define BB 2
#define TT 2048
#define DD 1024
#define HH 16
#define DHH 64
#define MM (BB*TT)
#define CC 64
#define NC (TT/CC)
#define NBH (BB*HH)
#define NCHT (NBH*NC)

// ---------------------------------------------------------------------------
// Scratch
// ---------------------------------------------------------------------------
__device__ __half g_qch[MM*DD];
__device__ __half g_kch[MM*DD];
__device__ __half g_vch[MM*DD];
__device__ float g_q [MM*DD];
__device__ float g_k [MM*DD];
__device__ float g_v [MM*DD];
__device__ float g_beta[BB*HH*TT];
__device__ float g_o [MM*DD];

__device__ float g_W [NCHT*CC*DHH];
__device__ float g_U0[NCHT*CC*DHH];
__device__ float g_M [NCHT*CC*CC];

__device__ __half g_xh[MM*DD];
__device__ __half g_oh[MM*DD];
__device__ __half g_wt[4][DD*DD];
__device__ float  g_wbt[HH*DD];     // Wb^T [16][1024]

// ---------------------------------------------------------------------------
// f32x2 helpers
// ---------------------------------------------------------------------------
__device__ __forceinline__ unsigned long long dup2(float x){
  unsigned long long r;
  unsigned u = __float_as_uint(x);
  asm("mov.b64 %0, {%1, %1};" : "=l"(r) : "r"(u));
  return r;
}
__device__ __forceinline__ void ffma2(unsigned long long &c, unsigned long long a, unsigned long long b){
  asm("fma.rn.f32x2 %0, %1, %2, %0;" : "+l"(c) : "l"(a), "l"(b));
}
__device__ __forceinline__ float2 unpk2(unsigned long long p){
  unsigned lo, hi;
  asm("mov.b64 {%0, %1}, %2;" : "=r"(lo), "=r"(hi) : "l"(p));
  return make_float2(__uint_as_float(lo), __uint_as_float(hi));
}

// ---------------------------------------------------------------------------
// smem / cp.async / mma helpers
// ---------------------------------------------------------------------------
__device__ __forceinline__ uint32_t smem_u32(const void* p){
  uint32_t a;
  asm("{ .reg .u64 t; cvta.to.shared.u64 t, %1; cvt.u32.u64 %0, t; }" : "=r"(a) : "l"(p));
  return a;
}
__device__ __forceinline__ void cpasync16(uint32_t dst, const void* src){
  asm volatile("cp.async.cg.shared.global [%0], [%1], 16;" :: "r"(dst), "l"(src));
}
__device__ __forceinline__ void cpasync_commit(){
  asm volatile("cp.async.commit_group;" ::: "memory");
}
__device__ __forceinline__ void ldm4(uint32_t* r, uint32_t addr){
  asm volatile("ldmatrix.sync.aligned.m8n8.x4.shared.b16 {%0,%1,%2,%3}, [%4];"
               : "=r"(r[0]), "=r"(r[1]), "=r"(r[2]), "=r"(r[3]) : "r"(addr));
}
__device__ __forceinline__ void mma16816h(float* d, const uint32_t* a, const uint32_t* b){
  asm volatile(
    "mma.sync.aligned.m16n8k16.row.col.f32.f16.f16.f32 "
    "{%0,%1,%2,%3}, {%4,%5,%6,%7}, {%8,%9}, {%0,%1,%2,%3};"
    : "+f"(d[0]), "+f"(d[1]), "+f"(d[2]), "+f"(d[3])
    : "r"(a[0]), "r"(a[1]), "r"(a[2]), "r"(a[3]), "r"(b[0]), "r"(b[1]));
}

// ---------------------------------------------------------------------------
// fp16 GEMM: KC=64, 3-stage cp.async, one sync/chunk, staged epilogue.
// (unchanged from 516us version)
// ---------------------------------------------------------------------------
#define GK   1024
#define KC   64
#define NCHG (GK/KC)
#define ROWB 144
#define MATB (128*ROWB)
#define STAGEB (2*MATB)
#define NSTAGE 3
#define GEMM_SMEM (NSTAGE*STAGEB)
#define EPI_PITCH 132

template<typename CT>
__global__ __launch_bounds__(256, 2)
void gemm_mma(const __half* __restrict__ A, const __half* __restrict__ Bbase,
              CT* __restrict__ C0, CT* __restrict__ C1, CT* __restrict__ C2)
{
  extern __shared__ char smem[];
  const uint32_t sb = smem_u32(smem);
  const int tid   = threadIdx.x;
  const int wid   = tid >> 5;
  const int lane  = tid & 31;
  const int warpM = wid & 1;
  const int warpN = wid >> 1;
  const int proj  = blockIdx.x >> 3;
  const int tileN = (blockIdx.x & 7) * 128;
  const int tileM = blockIdx.y * 128;
  const __half* B = Bbase + (size_t)proj * (DD*DD);
  CT* Cout = (proj == 0) ? C0 : ((proj == 1) ? C1 : C2);

  const __half* gsrc[2] = { A + (size_t)tileM * GK, B + (size_t)tileN * GK };

  auto load_stage = [&](int s, int kt){
    const uint32_t base = sb + s * STAGEB;
    #pragma unroll
    for (int i = 0; i < 8; i++){
      int cid = tid + i * 256;
      int mat = cid >> 10;
      int rem = cid & 1023;
      int row = rem >> 3, ch = rem & 7;
      cpasync16(base + mat * MATB + row * ROWB + ch * 16,
                gsrc[mat] + (size_t)row * GK + kt + ch * 8);
    }
  };

  float acc[4][4][4];
  #pragma unroll
  for (int mt = 0; mt < 4; mt++)
    #pragma unroll
    for (int nt = 0; nt < 4; nt++)
      #pragma unroll
      for (int j = 0; j < 4; j++) acc[mt][nt][j] = 0.f;

  const int aRow   = lane & 15;
  const int aKhalf = lane >> 4;
  const uint32_t aOff = (uint32_t)(warpM*64 + aRow) * ROWB + aKhalf * 16;
  const int bRow   = (lane & 7) + ((lane >> 4) << 3);
  const int bKhalf = (lane >> 3) & 1;
  const uint32_t bOff = (uint32_t)(warpN*32 + bRow) * ROWB + bKhalf * 16;

  load_stage(0, 0);    cpasync_commit();
  load_stage(1, KC);   cpasync_commit();

  for (int c = 0; c < NCHG; c++){
    if (c < NCHG - 1) asm volatile("cp.async.wait_group 1;" ::: "memory");
    else              asm volatile("cp.async.wait_group 0;" ::: "memory");
    __syncthreads();

    if (c + 2 < NCHG){
      int s = (c + 2) % 3;
      load_stage(s, (c + 2) * KC);
      cpasync_commit();
    }

    const uint32_t sbuf = sb + (c % 3) * STAGEB;
    #pragma unroll
    for (int ks = 0; ks < 4; ks++){
      const uint32_t koff = ks * 32;
      uint32_t ar[4][4], br[2][4];
      #pragma unroll
      for (int mt = 0; mt < 4; mt++)
        ldm4(ar[mt], sbuf + 0*MATB + aOff + mt*16*ROWB + koff);
      #pragma unroll
      for (int p = 0; p < 2; p++)
        ldm4(br[p], sbuf + 1*MATB + bOff + p*16*ROWB + koff);
      #pragma unroll
      for (int mt = 0; mt < 4; mt++)
        #pragma unroll
        for (int nt = 0; nt < 4; nt++)
          mma16816h(acc[mt][nt], ar[mt], &br[nt>>1][(nt&1)*2]);
    }
  }

  float* sOut = (float*)smem;
  const int lrow = lane >> 2;
  const int lcol = warpN*32 + (lane & 3)*2;
  #pragma unroll
  for (int mt = 0; mt < 4; mt++){
    if (mt == 0) __syncthreads();
    #pragma unroll
    for (int nt = 0; nt < 4; nt++){
      float* p0 = &sOut[(warpM*16 + lrow    ) * EPI_PITCH + lcol + nt*8];
      float* p1 = &sOut[(warpM*16 + lrow + 8) * EPI_PITCH + lcol + nt*8];
      p0[0] = acc[mt][nt][0]; p0[1] = acc[mt][nt][1];
      p1[0] = acc[mt][nt][2]; p1[1] = acc[mt][nt][3];
    }
    __syncthreads();
    #pragma unroll
    for (int i = 0; i < 4; i++){
      int idx = tid + i * 256;
      int r = idx >> 5, c4 = idx & 31;
      int gr = tileM + (r >> 4) * 64 + mt * 16 + (r & 15);
      float4 val = *(float4*)&sOut[r * EPI_PITCH + c4 * 4];
      if (sizeof(CT) == 4){
        *(float4*)&((float*)Cout)[(size_t)gr * GK + tileN + c4 * 4] = val;
      } else {
        __half2 h0 = __floats2half2_rn(val.x, val.y);
        __half2 h1 = __floats2half2_rn(val.z, val.w);
        uint32_t u0 = *(uint32_t*)&h0, u1 = *(uint32_t*)&h1;
        *(uint2*)&((__half*)Cout)[(size_t)gr * GK + tileN + c4 * 4] = make_uint2(u0, u1);
      }
    }
    __syncthreads();
  }
}

// ---------------------------------------------------------------------------
// fp32 -> fp16
// ---------------------------------------------------------------------------
__global__ void tohalf_kernel(const float* __restrict__ X, __half* __restrict__ H)
{
  int i = (blockIdx.x * 256 + threadIdx.x) * 4;
  float4 xv = *(const float4*)(X + i);
  *(__half2*)(H + i)     = __floats2half2_rn(xv.x, xv.y);
  *(__half2*)(H + i + 2) = __floats2half2_rn(xv.z, xv.w);
}

// ---------------------------------------------------------------------------
// Fused 4-way weight transpose + fp16
// ---------------------------------------------------------------------------
__global__ void wt4_kernel(const float* __restrict__ W0, const float* __restrict__ W1,
                           const float* __restrict__ W2, const float* __restrict__ W3,
                           __half* __restrict__ TH)
{
  const float* W = (blockIdx.z == 0) ? W0 : (blockIdx.z == 1) ? W1 : (blockIdx.z == 2) ? W2 : W3;
  __half* T = TH + (size_t)blockIdx.z * (DD*DD);
  __shared__ float tile[32][33];
  const int n0 = blockIdx.x * 32, k0 = blockIdx.y * 32;
  const int tx = threadIdx.x, ty = threadIdx.y;
  #pragma unroll
  for (int i = 0; i < 4; i++)
    tile[ty + i*8][tx] = W[(size_t)(k0 + ty + i*8) * DD + n0 + tx];
  __syncthreads();
  #pragma unroll
  for (int i = 0; i < 4; i++){
    float v = tile[tx][ty + i*8];
    T[(size_t)(n0 + ty + i*8) * DD + k0 + tx] = __float2half_rn(v);
  }
}

// ---------------------------------------------------------------------------
// Wb [1024][16] -> WbT [16][1024]
// ---------------------------------------------------------------------------
__global__ void wbt_kernel(const float* __restrict__ Wb, float* __restrict__ T)
{
  int idx = blockIdx.x * 256 + threadIdx.x;
  int k = idx >> 4, h = idx & 15;
  T[h * DD + k] = Wb[idx];
}

// ---------------------------------------------------------------------------
// beta: warp-per-row GEMV vs WbT (L1-resident), butterfly reduce.
// ---------------------------------------------------------------------------
__global__ __launch_bounds__(256)
void beta_kernel(const float* __restrict__ x, const float* __restrict__ WbT,
                 float* __restrict__ gb)
{
  const int w = threadIdx.x >> 5, lane = threadIdx.x & 31;
  const int m = blockIdx.x * 8 + w;
  const float* xr = x + (size_t)m * DD;

  float4 xv[8];
  #pragma unroll
  for (int i = 0; i < 8; i++) xv[i] = *(const float4*)&xr[lane*4 + i*128];

  float mine = 0.f;
  #pragma unroll
  for (int h = 0; h < 16; h++){
    const float* wr = WbT + h * DD;
    float acc = 0.f;
    #pragma unroll
    for (int i = 0; i < 8; i++){
      float4 wv = *(const float4*)&wr[lane*4 + i*128];
      acc += xv[i].x*wv.x + xv[i].y*wv.y + xv[i].z*wv.z + xv[i].w*wv.w;
    }
    #pragma unroll
    for (int off = 16; off > 0; off >>= 1)
      acc += __shfl_xor_sync(0xffffffffu, acc, off);
    if (lane == h) mine = acc;
  }
  if (lane < 16){
    int b = m >> 11, t = m & (TT-1);
    gb[((size_t)b * HH + lane) * TT + t] = 1.f / (1.f + __expf(-mine));
  }
}

// ---------------------------------------------------------------------------
// Fused conv (fp16 input) + SiLU (+ L2 norm for q,k). [M,D] -> [B,H,T,DH]
// ---------------------------------------------------------------------------
__global__ void conv3_kernel(const __half* __restrict__ Xq, const __half* __restrict__ Xk,
                             const __half* __restrict__ Xv,
                             const float* __restrict__ Wq, const float* __restrict__ Wk,
                             const float* __restrict__ Wv,
                             float* __restrict__ Yq, float* __restrict__ Yk,
                             float* __restrict__ Yv)
{
  const int which = blockIdx.y;
  const __half* X = (which == 0) ? Xq : (which == 1) ? Xk : Xv;
  const float*  W = (which == 0) ? Wq : (which == 1) ? Wk : Wv;
  float*        Y = (which == 0) ? Yq : (which == 1) ? Yk : Yv;
  const bool norm = (which < 2);

  const int m = blockIdx.x;
  const int b = m >> 11, t = m & (TT-1);
  const int tid = threadIdx.x;
  const int c0 = tid * 4;

  float warr[4][4];
  #pragma unroll
  for (int j = 0; j < 4; j++) {
    float4 wv = *(const float4*)&W[(size_t)(c0 + j) * 4];
    warr[j][0] = wv.x; warr[j][1] = wv.y; warr[j][2] = wv.z; warr[j][3] = wv.w;
  }
  float acc[4] = {0.f, 0.f, 0.f, 0.f};
  #pragma unroll
  for (int i = 0; i < 4; i++) {
    int tt = t - 3 + i;
    if (tt >= 0) {
      uint2 raw = *(const uint2*)&X[((size_t)(b * TT + tt)) * DD + c0];
      __half2 h0 = *(__half2*)&raw.x, h1 = *(__half2*)&raw.y;
      float2 f0 = __half22float2(h0), f1 = __half22float2(h1);
      acc[0] += warr[0][i] * f0.x;
      acc[1] += warr[1][i] * f0.y;
      acc[2] += warr[2][i] * f1.x;
      acc[3] += warr[3][i] * f1.y;
    }
  }
  float y[4];
  #pragma unroll
  for (int j = 0; j < 4; j++) {
    float s = 1.f / (1.f + __expf(-acc[j]));
    y[j] = acc[j] * s;
  }
  float scale = 1.f;
  if (norm) {
    float ss = y[0]*y[0] + y[1]*y[1] + y[2]*y[2] + y[3]*y[3];
    #pragma unroll
    for (int off = 8; off > 0; off >>= 1)
      ss += __shfl_xor_sync(0xffffffffu, ss, off, 16);
    scale = rsqrtf(ss + 1e-6f);
  }
  const int h = tid >> 4;
  const int dh0 = (tid & 15) * 4;
  *(float4*)&Y[(((size_t)(b * HH + h)) * TT + t) * DHH + dh0] =
      make_float4(y[0]*scale, y[1]*scale, y[2]*scale, y[3]*scale);
}

// ---------------------------------------------------------------------------
// WY precompute. Tinv now computed by exact Neumann doubling:
// (I+A)^-1 = Prod_{k=0..5} (I + P^(2^k)), P = -A (nilpotent), with
// sparsity-clipped j ranges. All 256 threads participate.
// ---------------------------------------------------------------------------
#define PRE_K  0
#define PRE_V  4096
#define PRE_Q  8192
#define PRE_KT 12288          // pitch 68; reused as Q (= P^s) during the solve
#define PRE_A  16640
#define PRE_TI 20736          // pitch 65; R accumulator -> Tinv
#define PRE_B  24896
#define PRE_TOT 24960

__global__ __launch_bounds__(256, 1)
void wy_pre(const float* __restrict__ gq, const float* __restrict__ gk,
            const float* __restrict__ gv, const float* __restrict__ gb,
            float* __restrict__ gW, float* __restrict__ gU0, float* __restrict__ gM)
{
  extern __shared__ float sm[];
  const int chunk = blockIdx.x;
  const int bh    = blockIdx.y;
  const int cid   = bh * NC + chunk;
  const int tid   = threadIdx.x;

  const float* K = gk + ((size_t)bh * TT + chunk * CC) * DHH;
  const float* Q = gq + ((size_t)bh * TT + chunk * CC) * DHH;
  const float* V = gv + ((size_t)bh * TT + chunk * CC) * DHH;
  const float* B = gb + (size_t)bh * TT + chunk * CC;

  #pragma unroll
  for (int i = 0; i < 4; i++){
    int idx  = tid + i * 256;
    int row  = idx >> 4, c4 = idx & 15;
    float4 kv = *(const float4*)&K[row * DHH + c4 * 4];
    *(float4*)&sm[PRE_K + row * 64 + c4 * 4] = kv;
    sm[PRE_KT + (c4*4+0) * 68 + row] = kv.x;
    sm[PRE_KT + (c4*4+1) * 68 + row] = kv.y;
    sm[PRE_KT + (c4*4+2) * 68 + row] = kv.z;
    sm[PRE_KT + (c4*4+3) * 68 + row] = kv.w;
    *(float4*)&sm[PRE_Q + row * 64 + c4 * 4] = *(const float4*)&Q[row * DHH + c4 * 4];
    *(float4*)&sm[PRE_V + row * 64 + c4 * 4] = *(const float4*)&V[row * DHH + c4 * 4];
  }
  if (tid < 64) sm[PRE_B + tid] = B[tid];
  __syncthreads();

  const int ty = tid >> 4, tx = tid & 15;
  const int r0 = ty * 4, c0 = tx * 4;

  // A = strict_tril(diag(b) K K^T); M = tril(Q K^T) -> global
  {
    unsigned long long accA[4][2], accM[4][2];
    #pragma unroll
    for (int m = 0; m < 4; m++){ accA[m][0]=accA[m][1]=accM[m][0]=accM[m][1]=0ull; }
    #pragma unroll 8
    for (int d = 0; d < 64; d++){
      ulonglong2 kc = *(const ulonglong2*)&sm[PRE_KT + d * 68 + c0];
      #pragma unroll
      for (int m = 0; m < 4; m++){
        unsigned long long kr = dup2(sm[PRE_K + (r0+m)*64 + d]);
        unsigned long long qr = dup2(sm[PRE_Q + (r0+m)*64 + d]);
        ffma2(accA[m][0], kr, kc.x);  ffma2(accA[m][1], kr, kc.y);
        ffma2(accM[m][0], qr, kc.x);  ffma2(accM[m][1], qr, kc.y);
      }
    }
    float* Mout = gM + (size_t)cid * (CC*CC);
    #pragma unroll
    for (int m = 0; m < 4; m++){
      const int t = r0 + m;
      const float bt = sm[PRE_B + t];
      float2 a01 = unpk2(accA[m][0]), a23 = unpk2(accA[m][1]);
      float2 m01 = unpk2(accM[m][0]), m23 = unpk2(accM[m][1]);
      float av[4] = {a01.x, a01.y, a23.x, a23.y};
      float mv[4] = {m01.x, m01.y, m23.x, m23.y};
      #pragma unroll
      for (int i = 0; i < 4; i++){
        const int s = c0 + i;
        sm[PRE_A + t*64 + s] = (s < t) ? bt * av[i] : 0.f;
        Mout[t*64 + s]       = (s <= t) ? mv[i] : 0.f;
      }
    }
  }
  __syncthreads();

  // R = I - A into PRE_TI ; Q = -A into PRE_KT (K^T no longer needed)
  #pragma unroll
  for (int m = 0; m < 4; m++)
    #pragma unroll
    for (int i = 0; i < 4; i++){
      float a = sm[PRE_A + (r0+m)*64 + c0+i];
      sm[PRE_KT + (r0+m)*68 + c0+i] = -a;
      sm[PRE_TI + (r0+m)*65 + c0+i] = ((r0+m) == (c0+i) ? 1.f : 0.f) - a;
    }
  __syncthreads();

  // Neumann doubling: 5 steps of { Q = Q*Q ; R += R*Q }
  #pragma unroll
  for (int k = 1; k <= 5; k++){
    const int sh = 1 << (k - 1);     // current Q = P^sh
    unsigned long long aq[4][2];
    #pragma unroll
    for (int m = 0; m < 4; m++){ aq[m][0] = 0ull; aq[m][1] = 0ull; }
    {
      int jlo = c0 + sh, jhi = r0 + 3 - sh;
      for (int j = jlo; j <= jhi; j++){
        ulonglong2 qv = *(const ulonglong2*)&sm[PRE_KT + j*68 + c0];
        #pragma unroll
        for (int m = 0; m < 4; m++){
          unsigned long long qs = dup2(sm[PRE_KT + (r0+m)*68 + j]);
          ffma2(aq[m][0], qs, qv.x);  ffma2(aq[m][1], qs, qv.y);
        }
      }
    }
    __syncthreads();
    #pragma unroll
    for (int m = 0; m < 4; m++){
      float2 q01 = unpk2(aq[m][0]), q23 = unpk2(aq[m][1]);
      sm[PRE_KT + (r0+m)*68 + c0+0] = q01.x;
      sm[PRE_KT + (r0+m)*68 + c0+1] = q01.y;
      sm[PRE_KT + (r0+m)*68 + c0+2] = q23.x;
      sm[PRE_KT + (r0+m)*68 + c0+3] = q23.y;
    }
    __syncthreads();

    unsigned long long ar_[4][2];
    #pragma unroll
    for (int m = 0; m < 4; m++){ ar_[m][0] = 0ull; ar_[m][1] = 0ull; }
    {
      int jlo = c0 + 2*sh;
      int jhi = r0 + 3; if (jhi > 63) jhi = 63;
      for (int j = jlo; j <= jhi; j++){
        ulonglong2 qv = *(const ulonglong2*)&sm[PRE_KT + j*68 + c0];
        #pragma unroll
        for (int m = 0; m < 4; m++){
          unsigned long long rs = dup2(sm[PRE_TI + (r0+m)*65 + j]);
          ffma2(ar_[m][0], rs, qv.x);  ffma2(ar_[m][1], rs, qv.y);
        }
      }
    }
    __syncthreads();
    #pragma unroll
    for (int m = 0; m < 4; m++){
      float2 r01 = unpk2(ar_[m][0]), r23 = unpk2(ar_[m][1]);
      sm[PRE_TI + (r0+m)*65 + c0+0] += r01.x;
      sm[PRE_TI + (r0+m)*65 + c0+1] += r01.y;
      sm[PRE_TI + (r0+m)*65 + c0+2] += r23.x;
      sm[PRE_TI + (r0+m)*65 + c0+3] += r23.y;
    }
    __syncthreads();
  }

  // W = Tinv diag(b) K ; U0 = Tinv diag(b) V
  {
    unsigned long long accW[4][2], accU[4][2];
    #pragma unroll
    for (int m = 0; m < 4; m++){ accW[m][0]=accW[m][1]=accU[m][0]=accU[m][1]=0ull; }
    #pragma unroll 8
    for (int j = 0; j < 64; j++){
      const float bj = sm[PRE_B + j];
      ulonglong2 k2 = *(const ulonglong2*)&sm[PRE_K + j*64 + c0];
      ulonglong2 v2 = *(const ulonglong2*)&sm[PRE_V + j*64 + c0];
      #pragma unroll
      for (int m = 0; m < 4; m++){
        unsigned long long tb = dup2(sm[PRE_TI + (r0+m)*65 + j] * bj);
        ffma2(accW[m][0], tb, k2.x);  ffma2(accW[m][1], tb, k2.y);
        ffma2(accU[m][0], tb, v2.x);  ffma2(accU[m][1], tb, v2.y);
      }
    }
    float* Wout = gW  + (size_t)cid * (CC*DHH);
    float* Uout = gU0 + (size_t)cid * (CC*DHH);
    #pragma unroll
    for (int m = 0; m < 4; m++){
      const int t = r0 + m;
      float2 w01 = unpk2(accW[m][0]), w23 = unpk2(accW[m][1]);
      float2 u01 = unpk2(accU[m][0]), u23 = unpk2(accU[m][1]);
      *(float4*)&Wout[t*64 + c0] = make_float4(w01.x, w01.y, w23.x, w23.y);
      *(float4*)&Uout[t*64 + c0] = make_float4(u01.x, u01.y, u23.x, u23.y);
    }
  }
}

// ---------------------------------------------------------------------------
// WY sequential pass: smem-staged operands; phases 1-2 use float4 row loads
// with register-dup2 (fewer LDS issues).
// ---------------------------------------------------------------------------
#define SP 20
#define SEQ_W  0
#define SEQ_M  4352
#define SEQ_Q  8704
#define SEQ_K  13056
#define SEQ_U0 17408
#define SEQ_STAGE 18432
#define SEQ_SS (2*SEQ_STAGE)
#define SEQ_SU (SEQ_SS + 64*SP)
#define SEQ_TOT (SEQ_SU + 64*SP)

__global__ __launch_bounds__(256, 1)
void wy_seq(const float* __restrict__ gq, const float* __restrict__ gk,
            const float* __restrict__ gW, const float* __restrict__ gU0,
            const float* __restrict__ gM, float* __restrict__ go)
{
  extern __shared__ float sm[];
  const uint32_t sb = smem_u32(sm);
  const int vsplit = blockIdx.x;
  const int bh     = blockIdx.y;
  const int colb   = vsplit * 16;
  const int tid    = threadIdx.x;
  const int trow   = tid >> 2;
  const int vo     = (tid & 3) * 4;

  float* sS = sm + SEQ_SS;
  float* sU = sm + SEQ_SU;

  auto load_chunk = [&](int st, int c){
    const size_t cid = (size_t)bh * NC + c;
    const float* srcs[4] = { gW + cid * (CC*DHH), gM + cid * (CC*CC),
                             gq + ((size_t)bh * TT + c * CC) * DHH,
                             gk + ((size_t)bh * TT + c * CC) * DHH };
    const uint32_t stb = sb + (st * SEQ_STAGE) * 4;
    #pragma unroll
    for (int i = 0; i < 16; i++){
      int id = tid + i * 256;
      int mat = id >> 10, rem = id & 1023;
      int row = rem >> 4, c4 = rem & 15;
      cpasync16(stb + (mat * 4352 + row * 68 + c4 * 4) * 4,
                srcs[mat] + (size_t)row * 64 + c4 * 4);
    }
    {
      int row = tid >> 2, c4 = tid & 3;
      cpasync16(stb + (SEQ_U0 + row * 16 + c4 * 4) * 4,
                gU0 + cid * (CC*DHH) + (size_t)row * 64 + colb + c4 * 4);
    }
  };

  for (int i = tid; i < 64 * SP; i += 256){ sS[i] = 0.f; }
  load_chunk(0, 0); cpasync_commit();
  __syncthreads();

  for (int c = 0; c < NC; c++){
    const int st = c & 1;
    if (c + 1 < NC){ load_chunk(st ^ 1, c + 1); cpasync_commit();
                     asm volatile("cp.async.wait_group 1;" ::: "memory"); }
    else           { asm volatile("cp.async.wait_group 0;" ::: "memory"); }
    __syncthreads();

    const float* cW  = sm + st * SEQ_STAGE + SEQ_W;
    const float* cM  = sm + st * SEQ_STAGE + SEQ_M;
    const float* cQ  = sm + st * SEQ_STAGE + SEQ_Q;
    const float* cK  = sm + st * SEQ_STAGE + SEQ_K;
    const float* cU0 = sm + st * SEQ_STAGE + SEQ_U0;
    float* Op = go + ((size_t)bh * TT + c * CC) * DHH + colb;

    // phase 1: U = U0 - W S  (float4 row loads of W)
    {
      float4 u0 = *(const float4*)&cU0[trow*16 + vo];
      unsigned long long a0, a1;
      { unsigned lo0=__float_as_uint(u0.x), hi0=__float_as_uint(u0.y);
        unsigned lo1=__float_as_uint(u0.z), hi1=__float_as_uint(u0.w);
        asm("mov.b64 %0, {%1, %2};" : "=l"(a0) : "r"(lo0), "r"(hi0));
        asm("mov.b64 %0, {%1, %2};" : "=l"(a1) : "r"(lo1), "r"(hi1)); }
      #pragma unroll 4
      for (int kk = 0; kk < 64; kk += 4){
        float4 w4 = *(const float4*)&cW[trow*68 + kk];
        ulonglong2 s0 = *(const ulonglong2*)&sS[(kk+0)*SP + vo];
        ulonglong2 s1 = *(const ulonglong2*)&sS[(kk+1)*SP + vo];
        ulonglong2 s2 = *(const ulonglong2*)&sS[(kk+2)*SP + vo];
        ulonglong2 s3 = *(const ulonglong2*)&sS[(kk+3)*SP + vo];
        unsigned long long w0 = dup2(-w4.x), w1 = dup2(-w4.y);
        unsigned long long w2 = dup2(-w4.z), w3 = dup2(-w4.w);
        ffma2(a0, w0, s0.x);  ffma2(a1, w0, s0.y);
        ffma2(a0, w1, s1.x);  ffma2(a1, w1, s1.y);
        ffma2(a0, w2, s2.x);  ffma2(a1, w2, s2.y);
        ffma2(a0, w3, s3.x);  ffma2(a1, w3, s3.y);
      }
      *(ulonglong2*)&sU[trow*SP + vo] = make_ulonglong2(a0, a1);
    }
    __syncthreads();

    // phase 2: O = Q S + M U  (float4 row loads of Q, M)
    {
      unsigned long long a0 = 0ull, a1 = 0ull;
      #pragma unroll 4
      for (int j = 0; j < 64; j += 4){
        float4 q4 = *(const float4*)&cQ[trow*68 + j];
        ulonglong2 s0 = *(const ulonglong2*)&sS[(j+0)*SP + vo];
        ulonglong2 s1 = *(const ulonglong2*)&sS[(j+1)*SP + vo];
        ulonglong2 s2 = *(const ulonglong2*)&sS[(j+2)*SP + vo];
        ulonglong2 s3 = *(const ulonglong2*)&sS[(j+3)*SP + vo];
        unsigned long long q0 = dup2(q4.x), q1 = dup2(q4.y);
        unsigned long long q2 = dup2(q4.z), q3 = dup2(q4.w);
        ffma2(a0, q0, s0.x);  ffma2(a1, q0, s0.y);
        ffma2(a0, q1, s1.x);  ffma2(a1, q1, s1.y);
        ffma2(a0, q2, s2.x);  ffma2(a1, q2, s2.y);
        ffma2(a0, q3, s3.x);  ffma2(a1, q3, s3.y);
      }
      #pragma unroll 4
      for (int s = 0; s < 64; s += 4){
        float4 m4 = *(const float4*)&cM[trow*68 + s];
        ulonglong2 u0 = *(const ulonglong2*)&sU[(s+0)*SP + vo];
        ulonglong2 u1 = *(const ulonglong2*)&sU[(s+1)*SP + vo];
        ulonglong2 u2 = *(const ulonglong2*)&sU[(s+2)*SP + vo];
        ulonglong2 u3 = *(const ulonglong2*)&sU[(s+3)*SP + vo];
        unsigned long long m0 = dup2(m4.x), m1 = dup2(m4.y);
        unsigned long long m2 = dup2(m4.z), m3 = dup2(m4.w);
        ffma2(a0, m0, u0.x);  ffma2(a1, m0, u0.y);
        ffma2(a0, m1, u1.x);  ffma2(a1, m1, u1.y);
        ffma2(a0, m2, u2.x);  ffma2(a1, m2, u2.y);
        ffma2(a0, m3, u3.x);  ffma2(a1, m3, u3.y);
      }
      float2 o01 = unpk2(a0), o23 = unpk2(a1);
      *(float4*)&Op[trow*64 + vo] = make_float4(o01.x, o01.y, o23.x, o23.y);
    }
    __syncthreads();

    // phase 3: S += K^T U (column access -> scalar loads)
    {
      ulonglong2 sacc = *(const ulonglong2*)&sS[trow*SP + vo];
      unsigned long long a0 = sacc.x, a1 = sacc.y;
      #pragma unroll 8
      for (int t = 0; t < 64; t++){
        unsigned long long kd = dup2(cK[t*68 + trow]);
        ulonglong2 u2 = *(const ulonglong2*)&sU[t*SP + vo];
        ffma2(a0, kd, u2.x);  ffma2(a1, kd, u2.y);
      }
      *(ulonglong2*)&sS[trow*SP + vo] = make_ulonglong2(a0, a1);
    }
    __syncthreads();
  }
}

// ---------------------------------------------------------------------------
// Per-head RMSNorm * rms_g -> [M,D] fp16
// ---------------------------------------------------------------------------
__global__ void rmsnorm_kernel(const float* __restrict__ O, const float* __restrict__ g,
                               __half* __restrict__ YH)
{
  const int m = blockIdx.x;
  const int b = m >> 11, t = m & (TT-1);
  const int tid = threadIdx.x;
  const int h = tid >> 4;
  const int dh0 = (tid & 15) * 4;

  float4 ov = *(const float4*)&O[(((size_t)(b * HH + h)) * TT + t) * DHH + dh0];
  float ss = ov.x*ov.x + ov.y*ov.y + ov.z*ov.z + ov.w*ov.w;
  #pragma unroll
  for (int off = 8; off > 0; off >>= 1)
    ss += __shfl_xor_sync(0xffffffffu, ss, off, 16);
  float sc = rsqrtf(ss * (1.f / 64.f) + 1e-6f);
  float4 gv = *(const float4*)&g[dh0];
  size_t base = (size_t)m * DD + tid * 4;
  *(__half2*)(YH + base)     = __floats2half2_rn(ov.x * sc * gv.x, ov.y * sc * gv.y);
  *(__half2*)(YH + base + 2) = __floats2half2_rn(ov.z * sc * gv.z, ov.w * sc * gv.w);
}

// ---------------------------------------------------------------------------
// Launch
// ---------------------------------------------------------------------------
extern "C" void kernel_launch(void* const* d_in, const int* in_sizes, int n_in,
                              void* d_out, int out_size)
{
  (void)in_sizes; (void)n_in; (void)out_size;
  const float* x  = (const float*)d_in[0];
  const float* Wq = (const float*)d_in[1];
  const float* Wk = (const float*)d_in[2];
  const float* Wv = (const float*)d_in[3];
  const float* Wb = (const float*)d_in[4];
  const float* cq = (const float*)d_in[5];
  const float* ck = (const float*)d_in[6];
  const float* cv = (const float*)d_in[7];
  const float* rg = (const float*)d_in[8];
  const float* Wo = (const float*)d_in[9];
  float* out = (float*)d_out;

  float *q, *k, *v, *beta, *o, *gW, *gU0, *gM, *wbt;
  __half *qch, *kch, *vch, *xh, *oh, *wt;
  cudaGetSymbolAddress((void**)&qch, g_qch);
  cudaGetSymbolAddress((void**)&kch, g_kch);
  cudaGetSymbolAddress((void**)&vch, g_vch);
  cudaGetSymbolAddress((void**)&q,   g_q);
  cudaGetSymbolAddress((void**)&k,   g_k);
  cudaGetSymbolAddress((void**)&v,   g_v);
  cudaGetSymbolAddress((void**)&beta, g_beta);
  cudaGetSymbolAddress((void**)&o,   g_o);
  cudaGetSymbolAddress((void**)&gW,  g_W);
  cudaGetSymbolAddress((void**)&gU0, g_U0);
  cudaGetSymbolAddress((void**)&gM,  g_M);
  cudaGetSymbolAddress((void**)&xh,  g_xh);
  cudaGetSymbolAddress((void**)&oh,  g_oh);
  cudaGetSymbolAddress((void**)&wt,  g_wt);
  cudaGetSymbolAddress((void**)&wbt, g_wbt);

  cudaFuncSetAttribute(gemm_mma<__half>, cudaFuncAttributeMaxDynamicSharedMemorySize, GEMM_SMEM);
  cudaFuncSetAttribute(gemm_mma<float>,  cudaFuncAttributeMaxDynamicSharedMemorySize, GEMM_SMEM);
  cudaFuncSetAttribute(wy_pre, cudaFuncAttributeMaxDynamicSharedMemorySize, PRE_TOT * 4);
  cudaFuncSetAttribute(wy_seq, cudaFuncAttributeMaxDynamicSharedMemorySize, SEQ_TOT * 4);

  const size_t WSZ = (size_t)DD * DD;

  tohalf_kernel<<<MM * DD / 1024, 256>>>(x, xh);
  wt4_kernel<<<dim3(32, 32, 4), dim3(32, 8)>>>(Wq, Wk, Wv, Wo, wt);
  wbt_kernel<<<64, 256>>>(Wb, wbt);

  gemm_mma<__half><<<dim3(24, MM/128), 256, GEMM_SMEM>>>(xh, wt, qch, kch, vch);

  beta_kernel<<<MM/8, 256>>>(x, wbt, beta);
  conv3_kernel<<<dim3(MM, 3), 256>>>(qch, kch, vch, cq, ck, cv, q, k, v);

  wy_pre<<<dim3(NC, NBH), 256, PRE_TOT * 4>>>(q, k, v, beta, gW, gU0, gM);
  wy_seq<<<dim3(4, NBH), 256, SEQ_TOT * 4>>>(q, k, gW, gU0, gM, o);

  rmsnorm_kernel<<<MM, 256>>>(o, rg, oh);
  gemm_mma<float><<<dim3(8, MM/128), 256, GEMM_SMEM>>>(oh, wt + 3*WSZ, out, out, out);
}

// round 17
// speedup vs baseline: 1.0944x; 1.0944x over previous
#include <cuda_runtime.h>
#include <cuda_fp16.h>
#include <cstdint>

// Problem constants
#define BB 2
#define TT 2048
#define DD 1024
#define HH 16
#define DHH 64
#define MM (BB*TT)
#define CC 64
#define NC (TT/CC)
#define NBH (BB*HH)
#define NCHT (NBH*NC)

// ---------------------------------------------------------------------------
// Scratch
// ---------------------------------------------------------------------------
__device__ __half g_qch[MM*DD];
__device__ __half g_kch[MM*DD];
__device__ __half g_vch[MM*DD];
__device__ float g_q [MM*DD];
__device__ float g_k [MM*DD];
__device__ float g_v [MM*DD];
__device__ float g_beta[BB*HH*TT];
__device__ float g_o [MM*DD];

__device__ float g_W [NCHT*CC*DHH];
__device__ float g_U0[NCHT*CC*DHH];
__device__ float g_M [NCHT*CC*CC];

__device__ __half g_xh[MM*DD];
__device__ __half g_oh[MM*DD];
__device__ __half g_wt[4][DD*DD];
__device__ float  g_wbt[HH*DD];     // Wb^T [16][1024]

// ---------------------------------------------------------------------------
// f32x2 helpers
// ---------------------------------------------------------------------------
__device__ __forceinline__ unsigned long long dup2(float x){
  unsigned long long r;
  unsigned u = __float_as_uint(x);
  asm("mov.b64 %0, {%1, %1};" : "=l"(r) : "r"(u));
  return r;
}
__device__ __forceinline__ void ffma2(unsigned long long &c, unsigned long long a, unsigned long long b){
  asm("fma.rn.f32x2 %0, %1, %2, %0;" : "+l"(c) : "l"(a), "l"(b));
}
__device__ __forceinline__ float2 unpk2(unsigned long long p){
  unsigned lo, hi;
  asm("mov.b64 {%0, %1}, %2;" : "=r"(lo), "=r"(hi) : "l"(p));
  return make_float2(__uint_as_float(lo), __uint_as_float(hi));
}

// ---------------------------------------------------------------------------
// smem / cp.async / mma helpers
// ---------------------------------------------------------------------------
__device__ __forceinline__ uint32_t smem_u32(const void* p){
  uint32_t a;
  asm("{ .reg .u64 t; cvta.to.shared.u64 t, %1; cvt.u32.u64 %0, t; }" : "=r"(a) : "l"(p));
  return a;
}
__device__ __forceinline__ void cpasync16(uint32_t dst, const void* src){
  asm volatile("cp.async.cg.shared.global [%0], [%1], 16;" :: "r"(dst), "l"(src));
}
__device__ __forceinline__ void cpasync_commit(){
  asm volatile("cp.async.commit_group;" ::: "memory");
}
__device__ __forceinline__ void ldm4(uint32_t* r, uint32_t addr){
  asm volatile("ldmatrix.sync.aligned.m8n8.x4.shared.b16 {%0,%1,%2,%3}, [%4];"
               : "=r"(r[0]), "=r"(r[1]), "=r"(r[2]), "=r"(r[3]) : "r"(addr));
}
__device__ __forceinline__ void mma16816h(float* d, const uint32_t* a, const uint32_t* b){
  asm volatile(
    "mma.sync.aligned.m16n8k16.row.col.f32.f16.f16.f32 "
    "{%0,%1,%2,%3}, {%4,%5,%6,%7}, {%8,%9}, {%0,%1,%2,%3};"
    : "+f"(d[0]), "+f"(d[1]), "+f"(d[2]), "+f"(d[3])
    : "r"(a[0]), "r"(a[1]), "r"(a[2]), "r"(a[3]), "r"(b[0]), "r"(b[1]));
}

// ---------------------------------------------------------------------------
// fp16 GEMM: KC=64, 3-stage cp.async, one sync/chunk, staged epilogue.
// Heterogeneous grid: blocks with blockIdx.x >= nGemmBx run the beta GEMV
// (sigmoid(x@Wb)) instead — fills scheduler gaps under the GEMM.
// ---------------------------------------------------------------------------
#define GK   1024
#define KC   64
#define NCHG (GK/KC)
#define ROWB 144
#define MATB (128*ROWB)
#define STAGEB (2*MATB)
#define NSTAGE 3
#define GEMM_SMEM (NSTAGE*STAGEB)
#define EPI_PITCH 132

template<typename CT>
__global__ __launch_bounds__(256, 2)
void gemm_mma(const __half* __restrict__ A, const __half* __restrict__ Bbase,
              CT* __restrict__ C0, CT* __restrict__ C1, CT* __restrict__ C2,
              const float* __restrict__ xbeta, const float* __restrict__ WbT,
              float* __restrict__ gb, int nGemmBx)
{
  // ---- beta path (extra blocks) ----
  if ((int)blockIdx.x >= nGemmBx){
    const int w = threadIdx.x >> 5, lane = threadIdx.x & 31;
    const int betaBlk = (blockIdx.x - nGemmBx) * gridDim.y + blockIdx.y;  // 0..511
    const int m = betaBlk * 8 + w;
    const float* xr = xbeta + (size_t)m * DD;

    float4 xv[8];
    #pragma unroll
    for (int i = 0; i < 8; i++) xv[i] = *(const float4*)&xr[lane*4 + i*128];

    float mine = 0.f;
    #pragma unroll
    for (int h = 0; h < 16; h++){
      const float* wr = WbT + h * DD;
      float acc = 0.f;
      #pragma unroll
      for (int i = 0; i < 8; i++){
        float4 wv = *(const float4*)&wr[lane*4 + i*128];
        acc += xv[i].x*wv.x + xv[i].y*wv.y + xv[i].z*wv.z + xv[i].w*wv.w;
      }
      #pragma unroll
      for (int off = 16; off > 0; off >>= 1)
        acc += __shfl_xor_sync(0xffffffffu, acc, off);
      if (lane == h) mine = acc;
    }
    if (lane < 16){
      int b = m >> 11, t = m & (TT-1);
      gb[((size_t)b * HH + lane) * TT + t] = 1.f / (1.f + __expf(-mine));
    }
    return;
  }

  // ---- GEMM path ----
  extern __shared__ char smem[];
  const uint32_t sb = smem_u32(smem);
  const int tid   = threadIdx.x;
  const int wid   = tid >> 5;
  const int lane  = tid & 31;
  const int warpM = wid & 1;
  const int warpN = wid >> 1;
  const int proj  = blockIdx.x >> 3;
  const int tileN = (blockIdx.x & 7) * 128;
  const int tileM = blockIdx.y * 128;
  const __half* B = Bbase + (size_t)proj * (DD*DD);
  CT* Cout = (proj == 0) ? C0 : ((proj == 1) ? C1 : C2);

  const __half* gsrc[2] = { A + (size_t)tileM * GK, B + (size_t)tileN * GK };

  auto load_stage = [&](int s, int kt){
    const uint32_t base = sb + s * STAGEB;
    #pragma unroll
    for (int i = 0; i < 8; i++){
      int cid = tid + i * 256;
      int mat = cid >> 10;
      int rem = cid & 1023;
      int row = rem >> 3, ch = rem & 7;
      cpasync16(base + mat * MATB + row * ROWB + ch * 16,
                gsrc[mat] + (size_t)row * GK + kt + ch * 8);
    }
  };

  float acc[4][4][4];
  #pragma unroll
  for (int mt = 0; mt < 4; mt++)
    #pragma unroll
    for (int nt = 0; nt < 4; nt++)
      #pragma unroll
      for (int j = 0; j < 4; j++) acc[mt][nt][j] = 0.f;

  const int aRow   = lane & 15;
  const int aKhalf = lane >> 4;
  const uint32_t aOff = (uint32_t)(warpM*64 + aRow) * ROWB + aKhalf * 16;
  const int bRow   = (lane & 7) + ((lane >> 4) << 3);
  const int bKhalf = (lane >> 3) & 1;
  const uint32_t bOff = (uint32_t)(warpN*32 + bRow) * ROWB + bKhalf * 16;

  load_stage(0, 0);    cpasync_commit();
  load_stage(1, KC);   cpasync_commit();

  for (int c = 0; c < NCHG; c++){
    if (c < NCHG - 1) asm volatile("cp.async.wait_group 1;" ::: "memory");
    else              asm volatile("cp.async.wait_group 0;" ::: "memory");
    __syncthreads();

    if (c + 2 < NCHG){
      int s = (c + 2) % 3;
      load_stage(s, (c + 2) * KC);
      cpasync_commit();
    }

    const uint32_t sbuf = sb + (c % 3) * STAGEB;
    #pragma unroll
    for (int ks = 0; ks < 4; ks++){
      const uint32_t koff = ks * 32;
      uint32_t ar[4][4], br[2][4];
      #pragma unroll
      for (int mt = 0; mt < 4; mt++)
        ldm4(ar[mt], sbuf + 0*MATB + aOff + mt*16*ROWB + koff);
      #pragma unroll
      for (int p = 0; p < 2; p++)
        ldm4(br[p], sbuf + 1*MATB + bOff + p*16*ROWB + koff);
      #pragma unroll
      for (int mt = 0; mt < 4; mt++)
        #pragma unroll
        for (int nt = 0; nt < 4; nt++)
          mma16816h(acc[mt][nt], ar[mt], &br[nt>>1][(nt&1)*2]);
    }
  }

  float* sOut = (float*)smem;
  const int lrow = lane >> 2;
  const int lcol = warpN*32 + (lane & 3)*2;
  #pragma unroll
  for (int mt = 0; mt < 4; mt++){
    if (mt == 0) __syncthreads();
    #pragma unroll
    for (int nt = 0; nt < 4; nt++){
      float* p0 = &sOut[(warpM*16 + lrow    ) * EPI_PITCH + lcol + nt*8];
      float* p1 = &sOut[(warpM*16 + lrow + 8) * EPI_PITCH + lcol + nt*8];
      p0[0] = acc[mt][nt][0]; p0[1] = acc[mt][nt][1];
      p1[0] = acc[mt][nt][2]; p1[1] = acc[mt][nt][3];
    }
    __syncthreads();
    #pragma unroll
    for (int i = 0; i < 4; i++){
      int idx = tid + i * 256;
      int r = idx >> 5, c4 = idx & 31;
      int gr = tileM + (r >> 4) * 64 + mt * 16 + (r & 15);
      float4 val = *(float4*)&sOut[r * EPI_PITCH + c4 * 4];
      if (sizeof(CT) == 4){
        *(float4*)&((float*)Cout)[(size_t)gr * GK + tileN + c4 * 4] = val;
      } else {
        __half2 h0 = __floats2half2_rn(val.x, val.y);
        __half2 h1 = __floats2half2_rn(val.z, val.w);
        uint32_t u0 = *(uint32_t*)&h0, u1 = *(uint32_t*)&h1;
        *(uint2*)&((__half*)Cout)[(size_t)gr * GK + tileN + c4 * 4] = make_uint2(u0, u1);
      }
    }
    __syncthreads();
  }
}

// ---------------------------------------------------------------------------
// Fused prep: tohalf (x->fp16), 4x weight transpose+fp16, Wb transpose.
// Flat 256-thread blocks; role by blockIdx.x.
//   bx in [0, 4096)      : tohalf block
//   bx in [4096, 8192)   : wt4 tile; z = (bx-4096)>>10, t = (bx-4096)&1023
//   bx in [8192, 8256)   : wbt block (64 blocks)
// ---------------------------------------------------------------------------
__global__ __launch_bounds__(256)
void prep_kernel(const float* __restrict__ x,
                 const float* __restrict__ W0, const float* __restrict__ W1,
                 const float* __restrict__ W2, const float* __restrict__ W3,
                 const float* __restrict__ Wb,
                 __half* __restrict__ xh, __half* __restrict__ wt,
                 float* __restrict__ wbt)
{
  const int bx = blockIdx.x;
  const int tid = threadIdx.x;

  if (bx < 4096){
    int i = (bx * 256 + tid) * 4;
    float4 xv = *(const float4*)(x + i);
    *(__half2*)(xh + i)     = __floats2half2_rn(xv.x, xv.y);
    *(__half2*)(xh + i + 2) = __floats2half2_rn(xv.z, xv.w);
    return;
  }
  if (bx < 8192){
    int t = bx - 4096;
    int z = t >> 10;  t &= 1023;
    const float* W = (z == 0) ? W0 : (z == 1) ? W1 : (z == 2) ? W2 : W3;
    __half* T = wt + (size_t)z * (DD*DD);
    __shared__ float tile[32][33];
    const int n0 = (t & 31) * 32, k0 = (t >> 5) * 32;
    const int tx = tid & 31, ty = tid >> 5;
    #pragma unroll
    for (int i = 0; i < 4; i++)
      tile[ty + i*8][tx] = W[(size_t)(k0 + ty + i*8) * DD + n0 + tx];
    __syncthreads();
    #pragma unroll
    for (int i = 0; i < 4; i++){
      float v = tile[tx][ty + i*8];
      T[(size_t)(n0 + ty + i*8) * DD + k0 + tx] = __float2half_rn(v);
    }
    return;
  }
  {
    int idx = (bx - 8192) * 256 + tid;
    int k = idx >> 4, h = idx & 15;
    wbt[h * DD + k] = Wb[idx];
  }
}

// ---------------------------------------------------------------------------
// Fused conv (fp16 input) + SiLU (+ L2 norm for q,k). [M,D] -> [B,H,T,DH]
// ---------------------------------------------------------------------------
__global__ void conv3_kernel(const __half* __restrict__ Xq, const __half* __restrict__ Xk,
                             const __half* __restrict__ Xv,
                             const float* __restrict__ Wq, const float* __restrict__ Wk,
                             const float* __restrict__ Wv,
                             float* __restrict__ Yq, float* __restrict__ Yk,
                             float* __restrict__ Yv)
{
  const int which = blockIdx.y;
  const __half* X = (which == 0) ? Xq : (which == 1) ? Xk : Xv;
  const float*  W = (which == 0) ? Wq : (which == 1) ? Wk : Wv;
  float*        Y = (which == 0) ? Yq : (which == 1) ? Yk : Yv;
  const bool norm = (which < 2);

  const int m = blockIdx.x;
  const int b = m >> 11, t = m & (TT-1);
  const int tid = threadIdx.x;
  const int c0 = tid * 4;

  float warr[4][4];
  #pragma unroll
  for (int j = 0; j < 4; j++) {
    float4 wv = *(const float4*)&W[(size_t)(c0 + j) * 4];
    warr[j][0] = wv.x; warr[j][1] = wv.y; warr[j][2] = wv.z; warr[j][3] = wv.w;
  }
  float acc[4] = {0.f, 0.f, 0.f, 0.f};
  #pragma unroll
  for (int i = 0; i < 4; i++) {
    int tt = t - 3 + i;
    if (tt >= 0) {
      uint2 raw = *(const uint2*)&X[((size_t)(b * TT + tt)) * DD + c0];
      __half2 h0 = *(__half2*)&raw.x, h1 = *(__half2*)&raw.y;
      float2 f0 = __half22float2(h0), f1 = __half22float2(h1);
      acc[0] += warr[0][i] * f0.x;
      acc[1] += warr[1][i] * f0.y;
      acc[2] += warr[2][i] * f1.x;
      acc[3] += warr[3][i] * f1.y;
    }
  }
  float y[4];
  #pragma unroll
  for (int j = 0; j < 4; j++) {
    float s = 1.f / (1.f + __expf(-acc[j]));
    y[j] = acc[j] * s;
  }
  float scale = 1.f;
  if (norm) {
    float ss = y[0]*y[0] + y[1]*y[1] + y[2]*y[2] + y[3]*y[3];
    #pragma unroll
    for (int off = 8; off > 0; off >>= 1)
      ss += __shfl_xor_sync(0xffffffffu, ss, off, 16);
    scale = rsqrtf(ss + 1e-6f);
  }
  const int h = tid >> 4;
  const int dh0 = (tid & 15) * 4;
  *(float4*)&Y[(((size_t)(b * HH + h)) * TT + t) * DHH + dh0] =
      make_float4(y[0]*scale, y[1]*scale, y[2]*scale, y[3]*scale);
}

// ---------------------------------------------------------------------------
// WY precompute (serial triangular solve — the proven 516us version)
// ---------------------------------------------------------------------------
#define PRE_K  0
#define PRE_V  4096
#define PRE_Q  8192
#define PRE_KT 12288
#define PRE_A  16640
#define PRE_TI 20736
#define PRE_B  24896
#define PRE_TOT 24960

__global__ __launch_bounds__(256, 1)
void wy_pre(const float* __restrict__ gq, const float* __restrict__ gk,
            const float* __restrict__ gv, const float* __restrict__ gb,
            float* __restrict__ gW, float* __restrict__ gU0, float* __restrict__ gM)
{
  extern __shared__ float sm[];
  const int chunk = blockIdx.x;
  const int bh    = blockIdx.y;
  const int cid   = bh * NC + chunk;
  const int tid   = threadIdx.x;

  const float* K = gk + ((size_t)bh * TT + chunk * CC) * DHH;
  const float* Q = gq + ((size_t)bh * TT + chunk * CC) * DHH;
  const float* V = gv + ((size_t)bh * TT + chunk * CC) * DHH;
  const float* B = gb + (size_t)bh * TT + chunk * CC;

  #pragma unroll
  for (int i = 0; i < 4; i++){
    int idx  = tid + i * 256;
    int row  = idx >> 4, c4 = idx & 15;
    float4 kv = *(const float4*)&K[row * DHH + c4 * 4];
    *(float4*)&sm[PRE_K + row * 64 + c4 * 4] = kv;
    sm[PRE_KT + (c4*4+0) * 68 + row] = kv.x;
    sm[PRE_KT + (c4*4+1) * 68 + row] = kv.y;
    sm[PRE_KT + (c4*4+2) * 68 + row] = kv.z;
    sm[PRE_KT + (c4*4+3) * 68 + row] = kv.w;
    *(float4*)&sm[PRE_Q + row * 64 + c4 * 4] = *(const float4*)&Q[row * DHH + c4 * 4];
    *(float4*)&sm[PRE_V + row * 64 + c4 * 4] = *(const float4*)&V[row * DHH + c4 * 4];
  }
  if (tid < 64) sm[PRE_B + tid] = B[tid];
  for (int i = tid; i < 64*65; i += 256) sm[PRE_TI + i] = 0.f;
  __syncthreads();

  {
    const int ty = tid >> 4, tx = tid & 15;
    const int r0 = ty * 4, c0 = tx * 4;
    unsigned long long accA[4][2], accM[4][2];
    #pragma unroll
    for (int m = 0; m < 4; m++){ accA[m][0]=accA[m][1]=accM[m][0]=accM[m][1]=0ull; }
    #pragma unroll 8
    for (int d = 0; d < 64; d++){
      ulonglong2 kc = *(const ulonglong2*)&sm[PRE_KT + d * 68 + c0];
      #pragma unroll
      for (int m = 0; m < 4; m++){
        unsigned long long kr = dup2(sm[PRE_K + (r0+m)*64 + d]);
        unsigned long long qr = dup2(sm[PRE_Q + (r0+m)*64 + d]);
        ffma2(accA[m][0], kr, kc.x);  ffma2(accA[m][1], kr, kc.y);
        ffma2(accM[m][0], qr, kc.x);  ffma2(accM[m][1], qr, kc.y);
      }
    }
    float* Mout = gM + (size_t)cid * (CC*CC);
    #pragma unroll
    for (int m = 0; m < 4; m++){
      const int t = r0 + m;
      const float bt = sm[PRE_B + t];
      float2 a01 = unpk2(accA[m][0]), a23 = unpk2(accA[m][1]);
      float2 m01 = unpk2(accM[m][0]), m23 = unpk2(accM[m][1]);
      float av[4] = {a01.x, a01.y, a23.x, a23.y};
      float mv[4] = {m01.x, m01.y, m23.x, m23.y};
      #pragma unroll
      for (int i = 0; i < 4; i++){
        const int s = c0 + i;
        sm[PRE_A + t*64 + s] = (s < t) ? bt * av[i] : 0.f;
        Mout[t*64 + s]       = (s <= t) ? mv[i] : 0.f;
      }
    }
  }
  __syncthreads();

  if (tid < 64){
    const int c = tid;
    sm[PRE_TI + c*65 + c] = 1.f;
    for (int t = c + 1; t < 64; t++){
      float acc = 0.f;
      for (int j = c; j < t; j++)
        acc += sm[PRE_A + t*64 + j] * sm[PRE_TI + j*65 + c];
      sm[PRE_TI + t*65 + c] = -acc;
    }
  }
  __syncthreads();

  {
    const int ty = tid >> 4, tx = tid & 15;
    const int r0 = ty * 4, c0 = tx * 4;
    unsigned long long accW[4][2], accU[4][2];
    #pragma unroll
    for (int m = 0; m < 4; m++){ accW[m][0]=accW[m][1]=accU[m][0]=accU[m][1]=0ull; }
    #pragma unroll 8
    for (int j = 0; j < 64; j++){
      const float bj = sm[PRE_B + j];
      ulonglong2 k2 = *(const ulonglong2*)&sm[PRE_K + j*64 + c0];
      ulonglong2 v2 = *(const ulonglong2*)&sm[PRE_V + j*64 + c0];
      #pragma unroll
      for (int m = 0; m < 4; m++){
        unsigned long long tb = dup2(sm[PRE_TI + (r0+m)*65 + j] * bj);
        ffma2(accW[m][0], tb, k2.x);  ffma2(accW[m][1], tb, k2.y);
        ffma2(accU[m][0], tb, v2.x);  ffma2(accU[m][1], tb, v2.y);
      }
    }
    float* Wout = gW  + (size_t)cid * (CC*DHH);
    float* Uout = gU0 + (size_t)cid * (CC*DHH);
    #pragma unroll
    for (int m = 0; m < 4; m++){
      const int t = r0 + m;
      float2 w01 = unpk2(accW[m][0]), w23 = unpk2(accW[m][1]);
      float2 u01 = unpk2(accU[m][0]), u23 = unpk2(accU[m][1]);
      *(float4*)&Wout[t*64 + c0] = make_float4(w01.x, w01.y, w23.x, w23.y);
      *(float4*)&Uout[t*64 + c0] = make_float4(u01.x, u01.y, u23.x, u23.y);
    }
  }
}

// ---------------------------------------------------------------------------
// WY sequential pass (the proven 516us version: scalar-LDS dup2 operands)
// ---------------------------------------------------------------------------
#define SP 20
#define SEQ_W  0
#define SEQ_M  4352
#define SEQ_Q  8704
#define SEQ_K  13056
#define SEQ_U0 17408
#define SEQ_STAGE 18432
#define SEQ_SS (2*SEQ_STAGE)
#define SEQ_SU (SEQ_SS + 64*SP)
#define SEQ_TOT (SEQ_SU + 64*SP)

__global__ __launch_bounds__(256, 1)
void wy_seq(const float* __restrict__ gq, const float* __restrict__ gk,
            const float* __restrict__ gW, const float* __restrict__ gU0,
            const float* __restrict__ gM, float* __restrict__ go)
{
  extern __shared__ float sm[];
  const uint32_t sb = smem_u32(sm);
  const int vsplit = blockIdx.x;
  const int bh     = blockIdx.y;
  const int colb   = vsplit * 16;
  const int tid    = threadIdx.x;
  const int trow   = tid >> 2;
  const int vo     = (tid & 3) * 4;

  float* sS = sm + SEQ_SS;
  float* sU = sm + SEQ_SU;

  auto load_chunk = [&](int st, int c){
    const size_t cid = (size_t)bh * NC + c;
    const float* srcs[4] = { gW + cid * (CC*DHH), gM + cid * (CC*CC),
                             gq + ((size_t)bh * TT + c * CC) * DHH,
                             gk + ((size_t)bh * TT + c * CC) * DHH };
    const uint32_t stb = sb + (st * SEQ_STAGE) * 4;
    #pragma unroll
    for (int i = 0; i < 16; i++){
      int id = tid + i * 256;
      int mat = id >> 10, rem = id & 1023;
      int row = rem >> 4, c4 = rem & 15;
      cpasync16(stb + (mat * 4352 + row * 68 + c4 * 4) * 4,
                srcs[mat] + (size_t)row * 64 + c4 * 4);
    }
    {
      int row = tid >> 2, c4 = tid & 3;
      cpasync16(stb + (SEQ_U0 + row * 16 + c4 * 4) * 4,
                gU0 + cid * (CC*DHH) + (size_t)row * 64 + colb + c4 * 4);
    }
  };

  for (int i = tid; i < 64 * SP; i += 256){ sS[i] = 0.f; }
  load_chunk(0, 0); cpasync_commit();
  __syncthreads();

  for (int c = 0; c < NC; c++){
    const int st = c & 1;
    if (c + 1 < NC){ load_chunk(st ^ 1, c + 1); cpasync_commit();
                     asm volatile("cp.async.wait_group 1;" ::: "memory"); }
    else           { asm volatile("cp.async.wait_group 0;" ::: "memory"); }
    __syncthreads();

    const float* cW  = sm + st * SEQ_STAGE + SEQ_W;
    const float* cM  = sm + st * SEQ_STAGE + SEQ_M;
    const float* cQ  = sm + st * SEQ_STAGE + SEQ_Q;
    const float* cK  = sm + st * SEQ_STAGE + SEQ_K;
    const float* cU0 = sm + st * SEQ_STAGE + SEQ_U0;
    float* Op = go + ((size_t)bh * TT + c * CC) * DHH + colb;

    {
      float4 u0 = *(const float4*)&cU0[trow*16 + vo];
      unsigned long long a0, a1;
      { unsigned lo0=__float_as_uint(u0.x), hi0=__float_as_uint(u0.y);
        unsigned lo1=__float_as_uint(u0.z), hi1=__float_as_uint(u0.w);
        asm("mov.b64 %0, {%1, %2};" : "=l"(a0) : "r"(lo0), "r"(hi0));
        asm("mov.b64 %0, {%1, %2};" : "=l"(a1) : "r"(lo1), "r"(hi1)); }
      #pragma unroll 8
      for (int kk = 0; kk < 64; kk++){
        unsigned long long nw = dup2(-cW[trow*68 + kk]);
        ulonglong2 s2 = *(const ulonglong2*)&sS[kk*SP + vo];
        ffma2(a0, nw, s2.x);  ffma2(a1, nw, s2.y);
      }
      *(ulonglong2*)&sU[trow*SP + vo] = make_ulonglong2(a0, a1);
    }
    __syncthreads();

    {
      unsigned long long a0 = 0ull, a1 = 0ull;
      #pragma unroll 8
      for (int j = 0; j < 64; j++){
        unsigned long long qd = dup2(cQ[trow*68 + j]);
        ulonglong2 s2 = *(const ulonglong2*)&sS[j*SP + vo];
        ffma2(a0, qd, s2.x);  ffma2(a1, qd, s2.y);
      }
      #pragma unroll 8
      for (int s = 0; s < 64; s++){
        unsigned long long md = dup2(cM[trow*68 + s]);
        ulonglong2 u2 = *(const ulonglong2*)&sU[s*SP + vo];
        ffma2(a0, md, u2.x);  ffma2(a1, md, u2.y);
      }
      float2 o01 = unpk2(a0), o23 = unpk2(a1);
      *(float4*)&Op[trow*64 + vo] = make_float4(o01.x, o01.y, o23.x, o23.y);
    }
    __syncthreads();

    {
      ulonglong2 sacc = *(const ulonglong2*)&sS[trow*SP + vo];
      unsigned long long a0 = sacc.x, a1 = sacc.y;
      #pragma unroll 8
      for (int t = 0; t < 64; t++){
        unsigned long long kd = dup2(cK[t*68 + trow]);
        ulonglong2 u2 = *(const ulonglong2*)&sU[t*SP + vo];
        ffma2(a0, kd, u2.x);  ffma2(a1, kd, u2.y);
      }
      *(ulonglong2*)&sS[trow*SP + vo] = make_ulonglong2(a0, a1);
    }
    __syncthreads();
  }
}

// ---------------------------------------------------------------------------
// Per-head RMSNorm * rms_g -> [M,D] fp16
// ---------------------------------------------------------------------------
__global__ void rmsnorm_kernel(const float* __restrict__ O, const float* __restrict__ g,
                               __half* __restrict__ YH)
{
  const int m = blockIdx.x;
  const int b = m >> 11, t = m & (TT-1);
  const int tid = threadIdx.x;
  const int h = tid >> 4;
  const int dh0 = (tid & 15) * 4;

  float4 ov = *(const float4*)&O[(((size_t)(b * HH + h)) * TT + t) * DHH + dh0];
  float ss = ov.x*ov.x + ov.y*ov.y + ov.z*ov.z + ov.w*ov.w;
  #pragma unroll
  for (int off = 8; off > 0; off >>= 1)
    ss += __shfl_xor_sync(0xffffffffu, ss, off, 16);
  float sc = rsqrtf(ss * (1.f / 64.f) + 1e-6f);
  float4 gv = *(const float4*)&g[dh0];
  size_t base = (size_t)m * DD + tid * 4;
  *(__half2*)(YH + base)     = __floats2half2_rn(ov.x * sc * gv.x, ov.y * sc * gv.y);
  *(__half2*)(YH + base + 2) = __floats2half2_rn(ov.z * sc * gv.z, ov.w * sc * gv.w);
}

// ---------------------------------------------------------------------------
// Launch
// ---------------------------------------------------------------------------
extern "C" void kernel_launch(void* const* d_in, const int* in_sizes, int n_in,
                              void* d_out, int out_size)
{
  (void)in_sizes; (void)n_in; (void)out_size;
  const float* x  = (const float*)d_in[0];
  const float* Wq = (const float*)d_in[1];
  const float* Wk = (const float*)d_in[2];
  const float* Wv = (const float*)d_in[3];
  const float* Wb = (const float*)d_in[4];
  const float* cq = (const float*)d_in[5];
  const float* ck = (const float*)d_in[6];
  const float* cv = (const float*)d_in[7];
  const float* rg = (const float*)d_in[8];
  const float* Wo = (const float*)d_in[9];
  float* out = (float*)d_out;

  float *q, *k, *v, *beta, *o, *gW, *gU0, *gM, *wbt;
  __half *qch, *kch, *vch, *xh, *oh, *wt;
  cudaGetSymbolAddress((void**)&qch, g_qch);
  cudaGetSymbolAddress((void**)&kch, g_kch);
  cudaGetSymbolAddress((void**)&vch, g_vch);
  cudaGetSymbolAddress((void**)&q,   g_q);
  cudaGetSymbolAddress((void**)&k,   g_k);
  cudaGetSymbolAddress((void**)&v,   g_v);
  cudaGetSymbolAddress((void**)&beta, g_beta);
  cudaGetSymbolAddress((void**)&o,   g_o);
  cudaGetSymbolAddress((void**)&gW,  g_W);
  cudaGetSymbolAddress((void**)&gU0, g_U0);
  cudaGetSymbolAddress((void**)&gM,  g_M);
  cudaGetSymbolAddress((void**)&xh,  g_xh);
  cudaGetSymbolAddress((void**)&oh,  g_oh);
  cudaGetSymbolAddress((void**)&wt,  g_wt);
  cudaGetSymbolAddress((void**)&wbt, g_wbt);

  cudaFuncSetAttribute(gemm_mma<__half>, cudaFuncAttributeMaxDynamicSharedMemorySize, GEMM_SMEM);
  cudaFuncSetAttribute(gemm_mma<float>,  cudaFuncAttributeMaxDynamicSharedMemorySize, GEMM_SMEM);
  cudaFuncSetAttribute(wy_pre, cudaFuncAttributeMaxDynamicSharedMemorySize, PRE_TOT * 4);
  cudaFuncSetAttribute(wy_seq, cudaFuncAttributeMaxDynamicSharedMemorySize, SEQ_TOT * 4);

  const size_t WSZ = (size_t)DD * DD;

  // fused prep: tohalf (4096) + wt4 (4096) + wbt (64)
  prep_kernel<<<8256, 256>>>(x, Wq, Wk, Wv, Wo, Wb, xh, wt, wbt);

  // fused QKV GEMM (bx<24) + beta GEMV (bx in [24,40))
  gemm_mma<__half><<<dim3(40, 32), 256, GEMM_SMEM>>>(xh, wt, qch, kch, vch,
                                                     x, wbt, beta, 24);

  conv3_kernel<<<dim3(MM, 3), 256>>>(qch, kch, vch, cq, ck, cv, q, k, v);

  wy_pre<<<dim3(NC, NBH), 256, PRE_TOT * 4>>>(q, k, v, beta, gW, gU0, gM);
  wy_seq<<<dim3(4, NBH), 256, SEQ_TOT * 4>>>(q, k, gW, gU0, gM, o);

  rmsnorm_kernel<<<MM, 256>>>(o, rg, oh);
  gemm_mma<float><<<dim3(8, MM/128), 256, GEMM_SMEM>>>(oh, wt + 3*WSZ, out, out, out,
                                                       nullptr, nullptr, nullptr, 8);
}